// round 4
// baseline (speedup 1.0000x reference)
#include <cuda_runtime.h>
#include <cuda_bf16.h>

// OrdinalRegressionLoss: mean over B x 4 of
//   max(x,0) - x*[j < target] + log1p(exp(-|x|))
// B = 8,388,608 rows, logits fp32 (B,4), targets int32 (B,).
// 160 MiB streamed once -> HBM-bound. Single fused kernel,
// stride-unrolled x4 for MLP with perfectly coalesced LDG.128s.

#define NBLOCKS 1184          // 148 SMs * 8
#define NTHREADS 256

__device__ float g_partials[NBLOCKS];
__device__ unsigned int g_count = 0;   // reset by last block -> graph-replay safe

__device__ __forceinline__ float bce_term(float x, float y) {
    float ax = fabsf(x);
    float sp = __logf(1.0f + __expf(-ax));   // log1p(exp(-ax)), ax>=0
    return fmaxf(x, 0.0f) - x * y + sp;
}

__device__ __forceinline__ float row_loss(float4 l, int t) {
    float s = bce_term(l.x, (float)(0 < t));
    s += bce_term(l.y, (float)(1 < t));
    s += bce_term(l.z, (float)(2 < t));
    s += bce_term(l.w, (float)(3 < t));
    return s;
}

__device__ __forceinline__ float block_reduce(float acc, float* ws) {
    #pragma unroll
    for (int o = 16; o > 0; o >>= 1)
        acc += __shfl_down_sync(0xffffffffu, acc, o);
    int lane = threadIdx.x & 31;
    int wid  = threadIdx.x >> 5;
    if (lane == 0) ws[wid] = acc;
    __syncthreads();
    float v = 0.0f;
    if (wid == 0) {
        v = (lane < NTHREADS / 32) ? ws[lane] : 0.0f;
        #pragma unroll
        for (int o = 4; o > 0; o >>= 1)
            v += __shfl_down_sync(0xffffffffu, v, o);
    }
    return v;   // valid at (wid==0, lane==0)
}

__global__ void __launch_bounds__(NTHREADS, 6)
ordinal_loss_fused(const float4* __restrict__ logits4,
                   const int* __restrict__ targets,
                   int nrows, float inv_total, float* __restrict__ out) {
    __shared__ float ws[NTHREADS / 32];
    __shared__ bool is_last;

    int tid = blockIdx.x * blockDim.x + threadIdx.x;
    int stride = gridDim.x * blockDim.x;
    float acc = 0.0f;

    // Unroll x4 across strides: 8 independent, perfectly coalesced loads in flight.
    int i = tid;
    for (; i + 3 * stride < nrows; i += 4 * stride) {
        float4 l0 = __ldcs(logits4 + i);
        float4 l1 = __ldcs(logits4 + i + stride);
        float4 l2 = __ldcs(logits4 + i + 2 * stride);
        float4 l3 = __ldcs(logits4 + i + 3 * stride);
        int t0 = __ldcs(targets + i);
        int t1 = __ldcs(targets + i + stride);
        int t2 = __ldcs(targets + i + 2 * stride);
        int t3 = __ldcs(targets + i + 3 * stride);
        acc += row_loss(l0, t0);
        acc += row_loss(l1, t1);
        acc += row_loss(l2, t2);
        acc += row_loss(l3, t3);
    }
    for (; i < nrows; i += stride)
        acc += row_loss(__ldcs(logits4 + i), __ldcs(targets + i));

    float bsum = block_reduce(acc, ws);
    if (threadIdx.x == 0) {
        g_partials[blockIdx.x] = bsum;
        __threadfence();
        unsigned int old = atomicAdd(&g_count, 1u);
        is_last = (old == gridDim.x - 1);
    }
    __syncthreads();

    if (is_last) {
        float a = 0.0f;
        for (int j = threadIdx.x; j < (int)gridDim.x; j += NTHREADS)
            a += g_partials[j];
        __syncthreads();          // ws reuse hazard
        float total = block_reduce(a, ws);
        if (threadIdx.x == 0) {
            out[0] = total * inv_total;
            g_count = 0;          // reset for next graph replay
        }
    }
}

extern "C" void kernel_launch(void* const* d_in, const int* in_sizes, int n_in,
                              void* d_out, int out_size) {
    const float4* logits4 = (const float4*)d_in[0];   // (B,4) fp32
    const int* targets    = (const int*)d_in[1];      // (B,) int32 on device
    float* out = (float*)d_out;

    int nrows = in_sizes[1];                          // B
    float inv_total = 1.0f / ((float)nrows * 4.0f);

    ordinal_loss_fused<<<NBLOCKS, NTHREADS>>>(logits4, targets, nrows, inv_total, out);
}

// round 5
// speedup vs baseline: 1.1096x; 1.1096x over previous
#include <cuda_runtime.h>
#include <cuda_bf16.h>

// OrdinalRegressionLoss: mean over B x 4 of
//   max(x,0) - x*[j < target] + log1p(exp(-|x|))
// B = 8,388,608 rows, logits fp32 (B,4), targets int32 (B,).
// 160 MiB streamed once -> HBM-bound.
// Mainloop = R2's measured-best simple grid-stride body (5.93 TB/s);
// tail = R3's measured-best fused threadfence reduction (saves 4.9 us launch).

#define NBLOCKS 1184          // 148 SMs * 8 blocks
#define NTHREADS 256

__device__ float g_partials[NBLOCKS];
__device__ unsigned int g_count = 0;   // reset by last block -> graph-replay safe

__device__ __forceinline__ float bce_term(float x, float y) {
    float ax = fabsf(x);
    float sp = __logf(1.0f + __expf(-ax));   // log1p(exp(-ax)), ax>=0
    return fmaxf(x, 0.0f) - x * y + sp;
}

__device__ __forceinline__ float row_loss(float4 l, int t) {
    float s = bce_term(l.x, (float)(0 < t));
    s += bce_term(l.y, (float)(1 < t));
    s += bce_term(l.z, (float)(2 < t));
    s += bce_term(l.w, (float)(3 < t));
    return s;
}

__device__ __forceinline__ float block_reduce(float acc, float* ws) {
    #pragma unroll
    for (int o = 16; o > 0; o >>= 1)
        acc += __shfl_down_sync(0xffffffffu, acc, o);
    int lane = threadIdx.x & 31;
    int wid  = threadIdx.x >> 5;
    if (lane == 0) ws[wid] = acc;
    __syncthreads();
    float v = 0.0f;
    if (wid == 0) {
        v = (lane < NTHREADS / 32) ? ws[lane] : 0.0f;
        #pragma unroll
        for (int o = 4; o > 0; o >>= 1)
            v += __shfl_down_sync(0xffffffffu, v, o);
    }
    return v;   // valid at (wid==0, lane==0)
}

__global__ void __launch_bounds__(NTHREADS, 8)
ordinal_loss_fused(const float4* __restrict__ logits4,
                   const int* __restrict__ targets,
                   int nrows, float inv_total, float* __restrict__ out) {
    __shared__ float ws[NTHREADS / 32];
    __shared__ bool is_last;

    float acc = 0.0f;
    int stride = gridDim.x * blockDim.x;
    // R2-measured-best mainloop: simple, dense, perfectly coalesced.
    for (int i = blockIdx.x * blockDim.x + threadIdx.x; i < nrows; i += stride) {
        float4 l = logits4[i];          // coalesced LDG.128
        int t = targets[i];             // coalesced LDG.32
        acc += row_loss(l, t);
    }

    float bsum = block_reduce(acc, ws);
    if (threadIdx.x == 0) {
        g_partials[blockIdx.x] = bsum;
        __threadfence();
        unsigned int old = atomicAdd(&g_count, 1u);
        is_last = (old == gridDim.x - 1);
    }
    __syncthreads();

    if (is_last) {
        float a = 0.0f;
        for (int j = threadIdx.x; j < (int)gridDim.x; j += NTHREADS)
            a += g_partials[j];
        __syncthreads();          // ws reuse hazard
        float total = block_reduce(a, ws);
        if (threadIdx.x == 0) {
            out[0] = total * inv_total;
            g_count = 0;          // reset for next graph replay
        }
    }
}

extern "C" void kernel_launch(void* const* d_in, const int* in_sizes, int n_in,
                              void* d_out, int out_size) {
    const float4* logits4 = (const float4*)d_in[0];   // (B,4) fp32
    const int* targets    = (const int*)d_in[1];      // (B,) int32 on device
    float* out = (float*)d_out;

    int nrows = in_sizes[1];                          // B
    float inv_total = 1.0f / ((float)nrows * 4.0f);

    ordinal_loss_fused<<<NBLOCKS, NTHREADS>>>(logits4, targets, nrows, inv_total, out);
}